// round 2
// baseline (speedup 1.0000x reference)
#include <cuda_runtime.h>
#include <math.h>

#define BB 32
#define NREG 196
#define EE 512
#define HH 512
#define SEQ 64
#define VV 32000

#define NBLK 148
#define NTHR 256

// ---------------- scratch (device globals; no allocations) ----------------
__device__ float g_fmean[BB * EE];
__device__ float g_hbuf[2][BB * HH];
__device__ float g_c[BB * HH];
__device__ float g_ctx[BB * EE];
__device__ float g_x[BB * EE];
__device__ float g_Hall[SEQ * BB * HH];   // row (t*32+b), 4 MB
__device__ unsigned g_bar_count;          // zero-init; invariant: 0 outside barriers
__device__ unsigned g_bar_gen;            // monotonically increasing across replays (ok)

// ---------------- grid-wide barrier (persistent-kernel style) ----------------
__device__ __forceinline__ void gridbar() {
    __syncthreads();
    if (threadIdx.x == 0) {
        unsigned gen = *((volatile unsigned*)&g_bar_gen);
        __threadfence();
        if (atomicAdd(&g_bar_count, 1u) == (unsigned)(gridDim.x - 1)) {
            g_bar_count = 0;
            __threadfence();
            atomicAdd(&g_bar_gen, 1u);
        } else {
            while (*((volatile unsigned*)&g_bar_gen) == gen) { __nanosleep(64); }
        }
        __threadfence();
    }
    __syncthreads();
}

__device__ __forceinline__ float warpsum(float v) {
#pragma unroll
    for (int o = 16; o; o >>= 1) v += __shfl_xor_sync(0xffffffffu, v, o);
    return v;
}

// warp-cooperative dot over 512 floats (both pointers 16B-aligned)
__device__ __forceinline__ float warpdot512(const float* __restrict__ a,
                                            const float* __restrict__ b, int lane) {
    float s = 0.f;
#pragma unroll
    for (int c = 0; c < 4; c++) {
        float4 av = *(const float4*)(a + c * 128 + lane * 4);
        float4 bv = *(const float4*)(b + c * 128 + lane * 4);
        s += av.x * bv.x + av.y * bv.y + av.z * bv.z + av.w * bv.w;
    }
    return s;
}

// ---------------- persistent recurrence kernel ----------------
__global__ void __launch_bounds__(NTHR) recurrence_kernel(
    const float* __restrict__ features, const int* __restrict__ captions,
    const float* __restrict__ embed_W,
    const float* __restrict__ ihW, const float* __restrict__ ihb,
    const float* __restrict__ icW, const float* __restrict__ icb,
    const float* __restrict__ rW,  const float* __restrict__ rb,
    const float* __restrict__ Wih, const float* __restrict__ Whh,
    const float* __restrict__ bih, const float* __restrict__ bhh)
{
    const int tid  = threadIdx.x;
    const int lane = tid & 31;
    const int gtid = blockIdx.x * NTHR + tid;
    const int wid_g  = gtid >> 5;
    const int nwarps = (gridDim.x * NTHR) >> 5;
    const int gstride = gridDim.x * NTHR;

    __shared__ __align__(16) float sh_h[HH];
    __shared__ float sh_sc[NREG];
    __shared__ float sh_red[NTHR / 32];

    // ---- Phase 0a: fmean[b][e] = mean_n features[b][n][e]
    for (int idx = gtid; idx < BB * EE; idx += gstride) {
        int b = idx >> 9, e = idx & 511;
        const float* fp = features + (size_t)b * NREG * EE + e;
        float s = 0.f;
        for (int n = 0; n < NREG; n++) s += fp[n * EE];
        g_fmean[idx] = s * (1.0f / NREG);
    }
    gridbar();

    // ---- Phase 0b: h0 / c0 (warp per output)
    for (int task = wid_g; task < 2 * BB * HH; task += nwarps) {
        int which = task & 1;
        int m = task >> 1;
        int b = m >> 9, eo = m & 511;
        const float* Wrow = (which ? icW : ihW) + (size_t)eo * EE;
        float s = warpsum(warpdot512(Wrow, g_fmean + b * EE, lane));
        if (lane == 0) {
            if (which) g_c[m] = s + icb[eo];
            else       g_hbuf[0][m] = s + ihb[eo];
        }
    }
    gridbar();

    for (int t = 0; t < SEQ; t++) {
        const float* hcur = g_hbuf[t & 1];
        float*       hnxt = g_hbuf[(t & 1) ^ 1];

        // ---- Phase A: attention (block b handles batch b)
        if (blockIdx.x < BB) {
            int b = blockIdx.x;
            for (int e = tid; e < HH; e += NTHR) sh_h[e] = hcur[b * HH + e];
            __syncthreads();
            int w = tid >> 5;
            for (int n = w; n < NREG; n += NTHR / 32) {
                float s = warpsum(warpdot512(features + ((size_t)b * NREG + n) * EE, sh_h, lane));
                if (lane == 0) sh_sc[n] = s;
            }
            __syncthreads();
            // softmax over 196
            float mx = -1e30f;
            for (int n = tid; n < NREG; n += NTHR) mx = fmaxf(mx, sh_sc[n]);
#pragma unroll
            for (int o = 16; o; o >>= 1) mx = fmaxf(mx, __shfl_xor_sync(0xffffffffu, mx, o));
            if (lane == 0) sh_red[w] = mx;
            __syncthreads();
            mx = sh_red[0];
#pragma unroll
            for (int i = 1; i < NTHR / 32; i++) mx = fmaxf(mx, sh_red[i]);
            __syncthreads();
            float ssum = 0.f;
            for (int n = tid; n < NREG; n += NTHR) {
                float ev = __expf(sh_sc[n] - mx);
                sh_sc[n] = ev;
                ssum += ev;
            }
            ssum = warpsum(ssum);
            if (lane == 0) sh_red[w] = ssum;
            __syncthreads();
            float tot = 0.f;
#pragma unroll
            for (int i = 0; i < NTHR / 32; i++) tot += sh_red[i];
            float inv = 1.0f / tot;
            __syncthreads();
            for (int n = tid; n < NREG; n += NTHR) sh_sc[n] *= inv;
            __syncthreads();
            // context[b][e] = sum_n attn[n] * features[b][n][e]
            for (int e = tid; e < EE; e += NTHR) {
                const float* fp = features + (size_t)b * NREG * EE + e;
                float s = 0.f;
                for (int n = 0; n < NREG; n++) s += sh_sc[n] * fp[n * EE];
                g_ctx[b * EE + e] = s;
            }
        }
        gridbar();

        // ---- Phase B: x = [ctx, emb_t] @ rW^T + rb  (warp per output)
        for (int task = wid_g; task < BB * EE; task += nwarps) {
            int b = task >> 9, eo = task & 511;
            int tok = captions[b * SEQ + t];
            const float* wr = rW + (size_t)eo * (EE + HH);
            float s = warpdot512(wr, g_ctx + b * EE, lane);
            const float* ew = embed_W + (size_t)tok * EE;
            float s2 = 0.f;
#pragma unroll
            for (int c = 0; c < 4; c++) {
                float4 av = *(const float4*)(wr + 512 + c * 128 + lane * 4);
                float4 bv = *(const float4*)(ew + c * 128 + lane * 4);
                s2 += av.x * bv.x + av.y * bv.y + av.z * bv.z + av.w * bv.w;
            }
            s += s2 * 22.62741699796952f;   // sqrt(512)
            s = warpsum(s);
            if (lane == 0) g_x[task] = s + rb[eo];
        }
        gridbar();

        // ---- Phase C: gates + LSTM cell (warp per (b,hidden))
        for (int task = wid_g; task < BB * HH; task += nwarps) {
            int b = task >> 9, hi = task & 511;
            const float* xb = g_x + b * EE;
            const float* hb = hcur + b * HH;
            float acc[4];
#pragma unroll
            for (int gi = 0; gi < 4; gi++) {
                int j = gi * HH + hi;
                float s = warpdot512(Wih + (size_t)j * EE, xb, lane)
                        + warpdot512(Whh + (size_t)j * HH, hb, lane);
                acc[gi] = warpsum(s);
            }
            if (lane == 0) {
                float iv = acc[0] + bih[hi]          + bhh[hi];
                float fv = acc[1] + bih[HH + hi]     + bhh[HH + hi];
                float gv = acc[2] + bih[2 * HH + hi] + bhh[2 * HH + hi];
                float ov = acc[3] + bih[3 * HH + hi] + bhh[3 * HH + hi];
                float si = 1.f / (1.f + __expf(-iv));
                float sf = 1.f / (1.f + __expf(-fv));
                float so = 1.f / (1.f + __expf(-ov));
                float c2 = sf * g_c[task] + si * tanhf(gv);
                float h2 = so * tanhf(c2);
                g_c[task] = c2;
                hnxt[task] = h2;
                g_Hall[((size_t)t * BB + b) * HH + hi] = h2;
            }
        }
        gridbar();
    }
}

// ---------------- output GEMM: out[2048,32000] = Hall @ out_W^T + out_b ----------------
#define BM 128
#define BN 128
#define BK 16
#define TM 8
#define TN 8

__global__ void __launch_bounds__(256) out_gemm(
    const float* __restrict__ outW, const float* __restrict__ outb,
    float* __restrict__ out)
{
    __shared__ __align__(16) float As[BK][BM];
    __shared__ __align__(16) float Bs[BK][BN];

    const int bn = blockIdx.x;      // 0..249
    const int bm = blockIdx.y;      // 0..15
    const int tid = threadIdx.x;
    const int tx = tid & 15;        // N direction
    const int ty = tid >> 4;        // M direction

    float acc[TM][TN];
#pragma unroll
    for (int i = 0; i < TM; i++)
#pragma unroll
        for (int j = 0; j < TN; j++) acc[i][j] = 0.f;

    const float* Abase = g_Hall + (size_t)bm * BM * 512;
    const float* Bbase = outW   + (size_t)bn * BN * 512;

    for (int k0 = 0; k0 < 512; k0 += BK) {
#pragma unroll
        for (int i = 0; i < 2; i++) {
            int f = tid + i * 256;          // 0..511 float4 slots
            int row = f >> 2;
            int cg  = (f & 3) * 4;
            float4 va = *(const float4*)(Abase + (size_t)row * 512 + k0 + cg);
            As[cg + 0][row] = va.x; As[cg + 1][row] = va.y;
            As[cg + 2][row] = va.z; As[cg + 3][row] = va.w;
            float4 vb = *(const float4*)(Bbase + (size_t)row * 512 + k0 + cg);
            Bs[cg + 0][row] = vb.x; Bs[cg + 1][row] = vb.y;
            Bs[cg + 2][row] = vb.z; Bs[cg + 3][row] = vb.w;
        }
        __syncthreads();
#pragma unroll
        for (int k = 0; k < BK; k++) {
            float a[TM], bf[TN];
#pragma unroll
            for (int i = 0; i < TM; i += 4) {
                float4 v = *(const float4*)&As[k][ty * TM + i];
                a[i] = v.x; a[i + 1] = v.y; a[i + 2] = v.z; a[i + 3] = v.w;
            }
#pragma unroll
            for (int j = 0; j < TN; j += 4) {
                float4 v = *(const float4*)&Bs[k][tx * TN + j];
                bf[j] = v.x; bf[j + 1] = v.y; bf[j + 2] = v.z; bf[j + 3] = v.w;
            }
#pragma unroll
            for (int i = 0; i < TM; i++)
#pragma unroll
                for (int j = 0; j < TN; j++) acc[i][j] += a[i] * bf[j];
        }
        __syncthreads();
    }

    // epilogue: row m = t*32 + b  ->  out[b][t][:]
#pragma unroll
    for (int i = 0; i < TM; i++) {
        int m = bm * BM + ty * TM + i;
        int tt = m >> 5, b = m & 31;
        float* orow = out + ((size_t)b * SEQ + tt) * VV + bn * BN + tx * TN;
        const float* brow = outb + bn * BN + tx * TN;
#pragma unroll
        for (int j = 0; j < TN; j += 4) {
            float4 bias = *(const float4*)(brow + j);
            float4 v;
            v.x = acc[i][j + 0] + bias.x;
            v.y = acc[i][j + 1] + bias.y;
            v.z = acc[i][j + 2] + bias.z;
            v.w = acc[i][j + 3] + bias.w;
            *(float4*)(orow + j) = v;
        }
    }
}

extern "C" void kernel_launch(void* const* d_in, const int* in_sizes, int n_in,
                              void* d_out, int out_size)
{
    const float* features = (const float*)d_in[0];
    const int*   captions = (const int*)d_in[1];
    const float* embed_W  = (const float*)d_in[2];
    const float* ihW = (const float*)d_in[3];
    const float* ihb = (const float*)d_in[4];
    const float* icW = (const float*)d_in[5];
    const float* icb = (const float*)d_in[6];
    const float* rW  = (const float*)d_in[7];
    const float* rb  = (const float*)d_in[8];
    const float* Wih = (const float*)d_in[9];
    const float* Whh = (const float*)d_in[10];
    const float* bih = (const float*)d_in[11];
    const float* bhh = (const float*)d_in[12];
    const float* outW = (const float*)d_in[13];
    const float* outb = (const float*)d_in[14];

    recurrence_kernel<<<NBLK, NTHR>>>(features, captions, embed_W,
                                      ihW, ihb, icW, icb, rW, rb,
                                      Wih, Whh, bih, bhh);
    dim3 grid(VV / BN, (SEQ * BB) / BM);
    out_gemm<<<grid, 256>>>(outW, outb, (float*)d_out);
}